// round 13
// baseline (speedup 1.0000x reference)
#include <cuda_runtime.h>
#include <stdint.h>

#define BATCH   16
#define NANCH   25200
#define NCLS    80
#define STRIDE  85
#define MAXC    1000
#define CONF_T  0.25f
#define IOU_T   0.45f
#define BINS    4096
#define SLOTCAP 64      // max entries per (batch,bin) bucket
#define CPB     8       // classes per block in k_nms
#define PSLICE  4       // CTAs per batch in k_prep

// k_score persistent pipeline
#define TAPB    64                       // anchors per tile
#define NTILES  ((BATCH * NANCH) / TAPB) // 6300
#define SGRID   592                      // one full wave at 4 CTAs/SM
#define TILE_BYTES (TAPB * STRIDE * 4)   // 21760

// ---------------- scratch (no allocations allowed) ----------------
__device__ __align__(16) unsigned int g_hist[BATCH * BINS];   // zero-init; zeroed in k_nms
__device__ unsigned long long g_bkey[BATCH * BINS * SLOTCAP]; // per-bin key buckets
__device__ float4             g_bbox[BATCH * BINS * SLOTCAP]; // per-bin raw xywh

// per-rank candidate data, [BATCH][MAXC]
__device__ float4 g_nbox[BATCH * MAXC];                       // offset box x1,y1,x2,y2
__device__ float  g_na  [BATCH * MAXC];                       // offset area
__device__ float4 g_rbox[BATCH * MAXC];                       // raw box x1,y1,x2,y2
__device__ float  g_conf[BATCH * MAXC];
__device__ unsigned int g_mask[BATCH * NCLS * 32];            // per-class rank bitmasks (zeroed in k_nms)
__device__ int    g_cnt[BATCH];                               // candidate count per batch

__device__ __forceinline__ unsigned smem_u32(const void* p)
{
    unsigned a;
    asm("{ .reg .u64 t; cvta.to.shared.u64 t, %1; cvt.u32.u64 %0, t; }"
        : "=r"(a) : "l"(p));
    return a;
}

__device__ __forceinline__ void bar_wait_parity(unsigned bar, unsigned parity)
{
    asm volatile(
        "{\n\t"
        ".reg .pred P;\n\t"
        "WAIT_%=:\n\t"
        "mbarrier.try_wait.parity.shared.b64 P, [%0], %1;\n\t"
        "@P bra DONE_%=;\n\t"
        "bra WAIT_%=;\n\t"
        "DONE_%=:\n\t"
        "}"
        :: "r"(bar), "r"(parity) : "memory");
}

__device__ __forceinline__ void tma_issue(unsigned bar, unsigned dst,
                                          const float* src)
{
    asm volatile("mbarrier.arrive.expect_tx.shared.b64 _, [%0], %1;"
                 :: "r"(bar), "r"(TILE_BYTES) : "memory");
    asm volatile(
        "cp.async.bulk.shared::cluster.global.mbarrier::complete_tx::bytes "
        "[%0], [%1], %2, [%3];"
        :: "r"(dst), "l"(src), "r"(TILE_BYTES), "r"(bar) : "memory");
}

// ---------------- K1: persistent double-buffered TMA + oct-per-anchor -------
__global__ void __launch_bounds__(512, 4) k_score(const float* __restrict__ pred)
{
    __shared__ __align__(16) float s[2][TAPB * STRIDE];   // 2 x 21760 B
    __shared__ __align__(8)  unsigned long long sBar[2];

    int tid = threadIdx.x;
    int bid = blockIdx.x;

    unsigned buf0 = smem_u32(s[0]);
    unsigned buf1 = smem_u32(s[1]);
    unsigned bar0 = smem_u32(&sBar[0]);
    unsigned bar1 = smem_u32(&sBar[1]);

    int n = (NTILES - bid + SGRID - 1) / SGRID;   // tiles for this CTA

    if (tid == 0) {
        asm volatile("mbarrier.init.shared.b64 [%0], %1;" :: "r"(bar0), "r"(1) : "memory");
        asm volatile("mbarrier.init.shared.b64 [%0], %1;" :: "r"(bar1), "r"(1) : "memory");
        asm volatile("fence.proxy.async.shared::cta;" ::: "memory");
        if (n > 0)
            tma_issue(bar0, buf0, pred + (size_t)bid * TAPB * STRIDE);
    }
    __syncthreads();

    int a = tid >> 3;            // anchor within tile (0..63)
    int h = tid & 7;             // oct lane: classes [10h, 10h+10)
    int base = a * STRIDE;
    int c0 = 5 + h * 10;

    unsigned phase0 = 0, phase1 = 0;

    for (int k = 0; k < n; ++k) {
        int tile = bid + k * SGRID;
        int kb   = k & 1;

        // prefetch next tile into the other buffer (its compute finished at k-1)
        if (k + 1 < n && tid == 0) {
            int nt = tile + SGRID;
            tma_issue(kb ? bar0 : bar1, kb ? buf0 : buf1,
                      pred + (size_t)nt * TAPB * STRIDE);
        }

        // wait for this tile's data
        if (kb) { bar_wait_parity(bar1, phase1); phase1 ^= 1; }
        else    { bar_wait_parity(bar0, phase0); phase0 ^= 1; }

        const float* sb = s[kb];
        float obj = sb[base + 4];            // uniform across the oct

        float bv = -1.0f; int bc = 0x7fffffff;
        if (obj > CONF_T) {
#pragma unroll
            for (int ci = 0; ci < 10; ++ci) {
                float p = __fmul_rn(sb[base + c0 + ci], obj);   // first-argmax (strict >)
                if (p > bv) { bv = p; bc = h * 10 + ci; }
            }
        }
        // value-only oct reduce (offsets < 8 stay within the anchor's oct)
        float cv = bv;
#pragma unroll
        for (int off = 1; off < 8; off <<= 1)
            cv = fmaxf(cv, __shfl_xor_sync(0xffffffffu, cv, off));
        // equality pick: lanes attaining the max contribute their first class;
        // min over class indices = exact global first-argmax
        int mycls = (bv == cv) ? bc : 0x7fffffff;
#pragma unroll
        for (int off = 1; off < 8; off <<= 1)
            mycls = min(mycls, __shfl_xor_sync(0xffffffffu, mycls, off));

        if (h == 0 && obj > CONF_T && cv > CONF_T) {
            unsigned bits = __float_as_uint(cv);
            // score in (0.25,1): bits in (0x3E800000,0x3F800000) -> 4096 exact bins
            int bin = (int)(bits >> 12) - 0x3E800;
            bin = bin < 0 ? 0 : (bin > BINS - 1 ? BINS - 1 : bin);

            int ga = tile * TAPB + a;
            int b  = ga / NANCH;
            int nn = ga - b * NANCH;

            unsigned slot = atomicAdd(&g_hist[b * BINS + bin], 1u);
            if (slot < SLOTCAP) {
                size_t sl = (size_t)(b * BINS + bin) * SLOTCAP + slot;
                // key = score_bits:32 | (0x7FFF-idx):15 | cls:8 (idx unique -> cls inert)
                g_bkey[sl] = ((unsigned long long)bits << 32)
                           | ((unsigned long long)(0x7FFFu - (unsigned)nn) << 8)
                           | (unsigned long long)(unsigned)mycls;
                g_bbox[sl] = make_float4(sb[base + 0], sb[base + 1],
                                         sb[base + 2], sb[base + 3]);
            }
        }

        __syncthreads();   // compute done before this buffer is overwritten
    }
}

// per-lane candidate finalize (rank -> global arrays + mask)
__device__ __forceinline__ void emit_candidate(
    int b, unsigned long long key, int rank, size_t slot)
{
    if (rank >= MAXC) return;
    unsigned bits = (unsigned)(key >> 32);
    int      cls  = (int)(key & 0xFF);
    float4   bx   = __ldg(&g_bbox[slot]);

    float hw = __fmul_rn(bx.z, 0.5f), hh = __fmul_rn(bx.w, 0.5f);
    float bx1 = __fsub_rn(bx.x, hw), by1 = __fsub_rn(bx.y, hh);
    float bx2 = __fadd_rn(bx.x, hw), by2 = __fadd_rn(bx.y, hh);
    float offc = __fmul_rn((float)cls, 4096.0f);      // exact (pow2)
    float ox1 = __fadd_rn(bx1, offc), oy1 = __fadd_rn(by1, offc);
    float ox2 = __fadd_rn(bx2, offc), oy2 = __fadd_rn(by2, offc);
    float area = __fmul_rn(__fsub_rn(ox2, ox1), __fsub_rn(oy2, oy1));

    int o = b * MAXC + rank;
    g_nbox[o] = make_float4(ox1, oy1, ox2, oy2);
    g_na[o]   = area;
    g_rbox[o] = make_float4(bx1, by1, bx2, by2);
    g_conf[o] = __uint_as_float(bits);
    atomicOr(&g_mask[(b * NCLS + cls) * 32 + (rank >> 5)], 1u << (rank & 31));
}

// ---------------- K2: prep — redundant scan, sliced ranking/emit ------------
__global__ void __launch_bounds__(1024) k_prep()
{
    int b     = blockIdx.x / PSLICE;
    int slice = blockIdx.x % PSLICE;
    int t     = threadIdx.x;
    int wrp   = t >> 5;
    int lane  = t & 31;

    __shared__ unsigned short sSufB[BINS];    // count of candidates in bins >= bin
    __shared__ unsigned int   sWarp[32];
    __shared__ int sT;

    // ---- A: load hist (NOT zeroed here — other slices still read it) ----
    uint4 hv = *(const uint4*)&g_hist[b * BINS + 4 * t];
    if (t == 0) sT = BINS;

    // ---- B: suffix sums via shuffle scan ----
    unsigned int csum = hv.x + hv.y + hv.z + hv.w;
    unsigned int v = csum;
#pragma unroll
    for (int off = 1; off < 32; off <<= 1) {
        unsigned int u = __shfl_down_sync(0xffffffffu, v, off);
        if (lane + off < 32) v += u;
    }
    if (lane == 0) sWarp[wrp] = v;
    __syncthreads();
    if (wrp == 0) {
        unsigned int w = sWarp[lane];
        unsigned int ws = w;
#pragma unroll
        for (int off = 1; off < 32; off <<= 1) {
            unsigned int u = __shfl_down_sync(0xffffffffu, ws, off);
            if (lane + off < 32) ws += u;
        }
        sWarp[lane] = ws - w;                 // exclusive (warps above)
    }
    __syncthreads();
    {
        unsigned int chunkSuf = v + sWarp[wrp];
        sSufB[4 * t + 0] = (unsigned short)chunkSuf;
        sSufB[4 * t + 1] = (unsigned short)(chunkSuf - hv.x);
        sSufB[4 * t + 2] = (unsigned short)(chunkSuf - hv.x - hv.y);
        sSufB[4 * t + 3] = (unsigned short)(chunkSuf - hv.x - hv.y - hv.z);
    }
    __syncthreads();

    // ---- C: threshold bin T ----
    unsigned int total = sSufB[0];
    unsigned int K = total < MAXC ? total : MAXC;
    if (K > 0) {
#pragma unroll
        for (int k = 0; k < 4; ++k) {
            int bi = 4 * t + k;
            unsigned int hi = sSufB[bi];
            unsigned int lo = (bi + 1 < BINS) ? sSufB[bi + 1] : 0u;
            if (hi >= K && lo < K) sT = bi;
        }
    }
    __syncthreads();
    int T = sT;

    if (slice == 0 && t == 0)
        g_cnt[b] = (T < BINS) ? (int)sSufB[T] : 0;

    // ---- DE: warp-per-bin register ranking + emit (1/PSLICE of bins) ----
    for (int bin = T + slice * 32 + wrp; bin < BINS; bin += 32 * PSLICE) {
        unsigned int off = (bin + 1 < BINS) ? sSufB[bin + 1] : 0u;
        int cb = (int)sSufB[bin] - (int)off;
        if (cb <= 0) continue;
        if (cb > SLOTCAP) cb = SLOTCAP;

        size_t sb = (size_t)(b * BINS + bin) * SLOTCAP;
        unsigned long long k1 = (lane < cb)      ? __ldg(&g_bkey[sb + lane])      : 0ull;
        unsigned long long k2 = (32 + lane < cb) ? __ldg(&g_bkey[sb + 32 + lane]) : 0ull;

        int n1 = cb < 32 ? cb : 32;
        int n2 = cb - n1;
        int r1 = 0, r2 = 0;
        for (int j = 0; j < n1; ++j) {
            unsigned long long kj = __shfl_sync(0xffffffffu, k1, j);
            r1 += (kj > k1) ? 1 : 0;
            r2 += (kj > k2) ? 1 : 0;
        }
        for (int j = 0; j < n2; ++j) {
            unsigned long long kj = __shfl_sync(0xffffffffu, k2, j);
            r1 += (kj > k1) ? 1 : 0;
            r2 += (kj > k2) ? 1 : 0;
        }

        if (lane < cb)      emit_candidate(b, k1, (int)off + r1, sb + lane);
        if (32 + lane < cb) emit_candidate(b, k2, (int)off + r2, sb + 32 + lane);
    }
}

// ---------------- K3: per-(batch,class) greedy NMS + housekeeping -----------
// Cross-class IoU is exactly 0 (class offsets are multiples of 4096, raw boxes
// in [-0.5,1.5]) -> reference greedy loop decomposes by class.
__global__ void __launch_bounds__(CPB * 32) k_nms(float* __restrict__ out)
{
    const int BLOCKS_PER_B = NCLS / CPB;              // 10
    int b    = blockIdx.x / BLOCKS_PER_B;
    int s    = blockIdx.x % BLOCKS_PER_B;
    int tid  = threadIdx.x;
    int wrp  = tid >> 5;
    int lane = tid & 31;
    int c    = s * CPB + wrp;

    __shared__ unsigned short sList[CPB][MAXC];       // 16000 B

    // housekeeping 1: zero this block's slice of g_hist (replay invariant)
    {
        int lo = s * 410;
        int hi = lo + 410; if (hi > BINS) hi = BINS;
        for (int i = lo + tid; i < hi; i += CPB * 32)
            g_hist[b * BINS + i] = 0u;
    }
    // housekeeping 2: zero rows for empty ranks (ranks are contiguous 0..cnt-1)
    int cnt = __ldg(&g_cnt[b]);
    {
        int start = cnt < MAXC ? cnt : MAXC;
        for (int r = start + s * (CPB * 32) + tid; r < MAXC; r += BLOCKS_PER_B * CPB * 32) {
            int o = b * MAXC + r;
            float2* row = (float2*)(out + (size_t)o * 6);
            row[0] = make_float2(0.f, 0.f);
            row[1] = make_float2(0.f, 0.f);
            row[2] = make_float2(0.f, 0.f);
            out[(size_t)BATCH * MAXC * 6 + o] = 0.f;
        }
    }

    // ---- gather: mask -> rank list in SMEM (and reset mask for replay) ----
    int mi = (b * NCLS + c) * 32 + lane;
    unsigned word = __ldg(&g_mask[mi]);
    g_mask[mi] = 0u;

    int pc = __popc(word);
    int incl = pc;
#pragma unroll
    for (int off = 1; off < 32; off <<= 1) {
        int u = __shfl_up_sync(0xffffffffu, incl, off);
        if (lane >= off) incl += u;
    }
    int excl  = incl - pc;
    int total = __shfl_sync(0xffffffffu, incl, 31);

    {
        unsigned m = word; int o = excl;
        while (m) {
            int p = __ffs(m) - 1;
            m &= m - 1;
            sList[wrp][o++] = (unsigned short)(lane * 32 + p);
        }
    }
    __syncwarp();

    // ---- greedy NMS: prefetch chunk to registers, serial loop on shuffles ----
    int   nk = 0;
    float kx1 = 0, ky1 = 0, kx2 = 0, ky2 = 0, ka = 0;

    for (int base = 0; base < total; base += 32) {
        int j = base + lane;
        int ri = 0;
        float4 qb = make_float4(0.f, 0.f, 0.f, 0.f);
        float  qa_ = 0.f;
        if (j < total) {
            ri = (int)sList[wrp][j];
            int o = b * MAXC + ri;
            qb  = __ldg(&g_nbox[o]);
            qa_ = __ldg(&g_na[o]);
        }
        int nl = total - base; if (nl > 32) nl = 32;
        int keptflag = 0;

        for (int k = 0; k < nl; ++k) {
            float qx1 = __shfl_sync(0xffffffffu, qb.x, k);
            float qy1 = __shfl_sync(0xffffffffu, qb.y, k);
            float qx2 = __shfl_sync(0xffffffffu, qb.z, k);
            float qy2 = __shfl_sync(0xffffffffu, qb.w, k);
            float qa  = __shfl_sync(0xffffffffu, qa_,  k);

            int sup = 0;
            if (lane < nk) {
                float ltx = fmaxf(kx1, qx1);
                float lty = fmaxf(ky1, qy1);
                float rbx = fminf(kx2, qx2);
                float rby = fminf(ky2, qy2);
                float ww  = fmaxf(__fsub_rn(rbx, ltx), 0.0f);
                float hh  = fmaxf(__fsub_rn(rby, lty), 0.0f);
                float inter = __fmul_rn(ww, hh);
                float den = __fadd_rn(__fsub_rn(__fadd_rn(ka, qa), inter), 1e-7f);
                sup = (__fdiv_rn(inter, den) > IOU_T) ? 1 : 0;
            }
            unsigned sb = __ballot_sync(0xffffffffu, sup);
            if (!sb) {
                if (lane == nk) { kx1 = qx1; ky1 = qy1; kx2 = qx2; ky2 = qy2; ka = qa; }
                nk++;
                if (lane == k) keptflag = 1;
            }
        }

        // owning lane writes its output row (outside the dependent chain)
        if (j < total) {
            int o = b * MAXC + ri;
            float* rs = out + (size_t)o * 6;
            if (keptflag) {
                float4 rb = __ldg(&g_rbox[o]);
                rs[0] = rb.x; rs[1] = rb.y; rs[2] = rb.z; rs[3] = rb.w;
                rs[4] = __ldg(&g_conf[o]);
                rs[5] = (float)c;
                out[(size_t)BATCH * MAXC * 6 + o] = 1.0f;
            } else {
                rs[0] = 0.f; rs[1] = 0.f; rs[2] = 0.f;
                rs[3] = 0.f; rs[4] = 0.f; rs[5] = 0.f;
                out[(size_t)BATCH * MAXC * 6 + o] = 0.f;
            }
        }
    }
}

// ---------------- launch ----------------
extern "C" void kernel_launch(void* const* d_in, const int* in_sizes, int n_in,
                              void* d_out, int out_size)
{
    (void)in_sizes; (void)n_in; (void)out_size;
    const float* pred = (const float*)d_in[0];
    float* out = (float*)d_out;

    k_score<<<SGRID, 512>>>(pred);                     // persistent, 1 wave
    k_prep<<<BATCH * PSLICE, 1024>>>();                // 64 blocks
    k_nms<<<BATCH * (NCLS / CPB), CPB * 32>>>(out);    // 160 blocks
}

// round 14
// speedup vs baseline: 1.0368x; 1.0368x over previous
#include <cuda_runtime.h>
#include <stdint.h>

#define BATCH   16
#define NANCH   25200
#define NCLS    80
#define STRIDE  85
#define MAXC    1000
#define CONF_T  0.25f
#define IOU_T   0.45f
#define BINS    4096
#define SLOTCAP 64      // max entries per (batch,bin) bucket
#define CPB     8       // classes per block in k_nms
#define PSLICE  8       // CTAs per batch in k_prep

// k_score persistent pipeline
#define TAPB    64                       // anchors per tile
#define NTILES  ((BATCH * NANCH) / TAPB) // 6300
#define SGRID   592                      // one full wave at 4 CTAs/SM
#define TILE_BYTES (TAPB * STRIDE * 4)   // 21760

// ---------------- scratch (no allocations allowed) ----------------
__device__ __align__(16) unsigned int g_hist[BATCH * BINS];   // zero-init; zeroed in k_nms
__device__ unsigned long long g_bkey[BATCH * BINS * SLOTCAP]; // per-bin key buckets
__device__ float4             g_bbox[BATCH * BINS * SLOTCAP]; // per-bin raw xywh

// per-rank candidate data, [BATCH][MAXC]
__device__ float4 g_nbox[BATCH * MAXC];                       // offset box x1,y1,x2,y2
__device__ float  g_na  [BATCH * MAXC];                       // offset area
__device__ float4 g_rbox[BATCH * MAXC];                       // raw box x1,y1,x2,y2
__device__ float  g_conf[BATCH * MAXC];
__device__ unsigned int g_mask[BATCH * NCLS * 32];            // per-class rank bitmasks (zeroed in k_nms)
__device__ int    g_cnt[BATCH];                               // candidate count per batch

__device__ __forceinline__ unsigned smem_u32(const void* p)
{
    unsigned a;
    asm("{ .reg .u64 t; cvta.to.shared.u64 t, %1; cvt.u32.u64 %0, t; }"
        : "=r"(a) : "l"(p));
    return a;
}

__device__ __forceinline__ void bar_wait_parity(unsigned bar, unsigned parity)
{
    asm volatile(
        "{\n\t"
        ".reg .pred P;\n\t"
        "WAIT_%=:\n\t"
        "mbarrier.try_wait.parity.shared.b64 P, [%0], %1;\n\t"
        "@P bra DONE_%=;\n\t"
        "bra WAIT_%=;\n\t"
        "DONE_%=:\n\t"
        "}"
        :: "r"(bar), "r"(parity) : "memory");
}

__device__ __forceinline__ void tma_issue(unsigned bar, unsigned dst,
                                          const float* src)
{
    asm volatile("mbarrier.arrive.expect_tx.shared.b64 _, [%0], %1;"
                 :: "r"(bar), "r"(TILE_BYTES) : "memory");
    asm volatile(
        "cp.async.bulk.shared::cluster.global.mbarrier::complete_tx::bytes "
        "[%0], [%1], %2, [%3];"
        :: "r"(dst), "l"(src), "r"(TILE_BYTES), "r"(bar) : "memory");
}

// ---------------- K1: persistent double-buffered TMA + oct-per-anchor -------
__global__ void __launch_bounds__(512, 4) k_score(const float* __restrict__ pred)
{
    __shared__ __align__(16) float s[2][TAPB * STRIDE];   // 2 x 21760 B
    __shared__ __align__(8)  unsigned long long sBar[2];

    int tid = threadIdx.x;
    int bid = blockIdx.x;

    unsigned buf0 = smem_u32(s[0]);
    unsigned buf1 = smem_u32(s[1]);
    unsigned bar0 = smem_u32(&sBar[0]);
    unsigned bar1 = smem_u32(&sBar[1]);

    int n = (NTILES - bid + SGRID - 1) / SGRID;   // tiles for this CTA

    if (tid == 0) {
        asm volatile("mbarrier.init.shared.b64 [%0], %1;" :: "r"(bar0), "r"(1) : "memory");
        asm volatile("mbarrier.init.shared.b64 [%0], %1;" :: "r"(bar1), "r"(1) : "memory");
        asm volatile("fence.proxy.async.shared::cta;" ::: "memory");
        if (n > 0)
            tma_issue(bar0, buf0, pred + (size_t)bid * TAPB * STRIDE);
    }
    __syncthreads();

    int a     = tid >> 3;        // anchor within tile (0..63)
    int h     = tid & 7;         // oct lane: classes [10h, 10h+10)
    int lane5 = tid & 31;
    int base  = a * STRIDE;
    int c0    = 5 + h * 10;

    unsigned phase0 = 0, phase1 = 0;

    for (int k = 0; k < n; ++k) {
        int tile = bid + k * SGRID;
        int kb   = k & 1;

        // prefetch next tile into the other buffer (its compute finished at k-1)
        if (k + 1 < n && tid == 0) {
            int nt = tile + SGRID;
            tma_issue(kb ? bar0 : bar1, kb ? buf0 : buf1,
                      pred + (size_t)nt * TAPB * STRIDE);
        }

        // wait for this tile's data
        if (kb) { bar_wait_parity(bar1, phase1); phase1 ^= 1; }
        else    { bar_wait_parity(bar0, phase0); phase0 ^= 1; }

        const float* sb = s[kb];
        float obj = sb[base + 4];            // uniform across the oct

        // per-lane value-only max (products >= 0)
        float lm = -1.0f;
        if (obj > CONF_T) {
            lm = 0.0f;
#pragma unroll
            for (int ci = 0; ci < 10; ++ci)
                lm = fmaxf(lm, __fmul_rn(sb[base + c0 + ci], obj));
        }
        // oct value reduce (offsets < 8 stay within the anchor's oct)
        float cv = lm;
#pragma unroll
        for (int off = 1; off < 8; off <<= 1)
            cv = fmaxf(cv, __shfl_xor_sync(0xffffffffu, cv, off));

        // elect the lowest attaining lane in the oct (= lowest class block);
        // bit-equality on identical __fmul_rn products -> exact attainers.
        unsigned att  = __ballot_sync(0xffffffffu, (lm == cv) && (cv > CONF_T));
        unsigned octm = (att >> (lane5 & ~7)) & 0xFFu;

        if (octm && (lane5 & 7) == (int)(__ffs(octm) - 1)) {
            // winner rescans its 10 products descending: final hit = first
            // (lowest ci) match = global first-argmax (jnp.argmax order)
            int cls = 0;
#pragma unroll
            for (int ci = 9; ci >= 0; --ci)
                if (__fmul_rn(sb[base + c0 + ci], obj) == cv) cls = h * 10 + ci;

            unsigned bits = __float_as_uint(cv);
            // score in (0.25,1): bits in (0x3E800000,0x3F800000) -> 4096 exact bins
            int bin = (int)(bits >> 12) - 0x3E800;
            bin = bin < 0 ? 0 : (bin > BINS - 1 ? BINS - 1 : bin);

            int ga = tile * TAPB + a;
            int b  = ga / NANCH;
            int nn = ga - b * NANCH;

            unsigned slot = atomicAdd(&g_hist[b * BINS + bin], 1u);
            if (slot < SLOTCAP) {
                size_t sl = (size_t)(b * BINS + bin) * SLOTCAP + slot;
                // key = score_bits:32 | (0x7FFF-idx):15 | cls:8 (idx unique -> cls inert)
                g_bkey[sl] = ((unsigned long long)bits << 32)
                           | ((unsigned long long)(0x7FFFu - (unsigned)nn) << 8)
                           | (unsigned long long)(unsigned)cls;
                g_bbox[sl] = make_float4(sb[base + 0], sb[base + 1],
                                         sb[base + 2], sb[base + 3]);
            }
        }

        __syncthreads();   // compute done before this buffer is overwritten
    }
}

// per-lane candidate finalize (rank -> global arrays + mask)
__device__ __forceinline__ void emit_candidate(
    int b, unsigned long long key, int rank, size_t slot)
{
    if (rank >= MAXC) return;
    unsigned bits = (unsigned)(key >> 32);
    int      cls  = (int)(key & 0xFF);
    float4   bx   = __ldg(&g_bbox[slot]);

    float hw = __fmul_rn(bx.z, 0.5f), hh = __fmul_rn(bx.w, 0.5f);
    float bx1 = __fsub_rn(bx.x, hw), by1 = __fsub_rn(bx.y, hh);
    float bx2 = __fadd_rn(bx.x, hw), by2 = __fadd_rn(bx.y, hh);
    float offc = __fmul_rn((float)cls, 4096.0f);      // exact (pow2)
    float ox1 = __fadd_rn(bx1, offc), oy1 = __fadd_rn(by1, offc);
    float ox2 = __fadd_rn(bx2, offc), oy2 = __fadd_rn(by2, offc);
    float area = __fmul_rn(__fsub_rn(ox2, ox1), __fsub_rn(oy2, oy1));

    int o = b * MAXC + rank;
    g_nbox[o] = make_float4(ox1, oy1, ox2, oy2);
    g_na[o]   = area;
    g_rbox[o] = make_float4(bx1, by1, bx2, by2);
    g_conf[o] = __uint_as_float(bits);
    atomicOr(&g_mask[(b * NCLS + cls) * 32 + (rank >> 5)], 1u << (rank & 31));
}

// ---------------- K2: prep — redundant scan, sliced ranking/emit ------------
__global__ void __launch_bounds__(1024) k_prep()
{
    int b     = blockIdx.x / PSLICE;
    int slice = blockIdx.x % PSLICE;
    int t     = threadIdx.x;
    int wrp   = t >> 5;
    int lane  = t & 31;

    __shared__ unsigned short sSufB[BINS];    // count of candidates in bins >= bin
    __shared__ unsigned int   sWarp[32];
    __shared__ int sT;

    // ---- A: load hist (NOT zeroed here — other slices still read it) ----
    uint4 hv = *(const uint4*)&g_hist[b * BINS + 4 * t];
    if (t == 0) sT = BINS;

    // ---- B: suffix sums via shuffle scan ----
    unsigned int csum = hv.x + hv.y + hv.z + hv.w;
    unsigned int v = csum;
#pragma unroll
    for (int off = 1; off < 32; off <<= 1) {
        unsigned int u = __shfl_down_sync(0xffffffffu, v, off);
        if (lane + off < 32) v += u;
    }
    if (lane == 0) sWarp[wrp] = v;
    __syncthreads();
    if (wrp == 0) {
        unsigned int w = sWarp[lane];
        unsigned int ws = w;
#pragma unroll
        for (int off = 1; off < 32; off <<= 1) {
            unsigned int u = __shfl_down_sync(0xffffffffu, ws, off);
            if (lane + off < 32) ws += u;
        }
        sWarp[lane] = ws - w;                 // exclusive (warps above)
    }
    __syncthreads();
    {
        unsigned int chunkSuf = v + sWarp[wrp];
        sSufB[4 * t + 0] = (unsigned short)chunkSuf;
        sSufB[4 * t + 1] = (unsigned short)(chunkSuf - hv.x);
        sSufB[4 * t + 2] = (unsigned short)(chunkSuf - hv.x - hv.y);
        sSufB[4 * t + 3] = (unsigned short)(chunkSuf - hv.x - hv.y - hv.z);
    }
    __syncthreads();

    // ---- C: threshold bin T ----
    unsigned int total = sSufB[0];
    unsigned int K = total < MAXC ? total : MAXC;
    if (K > 0) {
#pragma unroll
        for (int k = 0; k < 4; ++k) {
            int bi = 4 * t + k;
            unsigned int hi = sSufB[bi];
            unsigned int lo = (bi + 1 < BINS) ? sSufB[bi + 1] : 0u;
            if (hi >= K && lo < K) sT = bi;
        }
    }
    __syncthreads();
    int T = sT;

    if (slice == 0 && t == 0)
        g_cnt[b] = (T < BINS) ? (int)sSufB[T] : 0;

    // ---- DE: warp-per-bin register ranking + emit (1/PSLICE of bins) ----
    for (int bin = T + slice * 32 + wrp; bin < BINS; bin += 32 * PSLICE) {
        unsigned int off = (bin + 1 < BINS) ? sSufB[bin + 1] : 0u;
        int cb = (int)sSufB[bin] - (int)off;
        if (cb <= 0) continue;
        if (cb > SLOTCAP) cb = SLOTCAP;

        size_t sb = (size_t)(b * BINS + bin) * SLOTCAP;
        unsigned long long k1 = (lane < cb)      ? __ldg(&g_bkey[sb + lane])      : 0ull;
        unsigned long long k2 = (32 + lane < cb) ? __ldg(&g_bkey[sb + 32 + lane]) : 0ull;

        int n1 = cb < 32 ? cb : 32;
        int n2 = cb - n1;
        int r1 = 0, r2 = 0;
        for (int j = 0; j < n1; ++j) {
            unsigned long long kj = __shfl_sync(0xffffffffu, k1, j);
            r1 += (kj > k1) ? 1 : 0;
            r2 += (kj > k2) ? 1 : 0;
        }
        for (int j = 0; j < n2; ++j) {
            unsigned long long kj = __shfl_sync(0xffffffffu, k2, j);
            r1 += (kj > k1) ? 1 : 0;
            r2 += (kj > k2) ? 1 : 0;
        }

        if (lane < cb)      emit_candidate(b, k1, (int)off + r1, sb + lane);
        if (32 + lane < cb) emit_candidate(b, k2, (int)off + r2, sb + 32 + lane);
    }
}

// ---------------- K3: per-(batch,class) greedy NMS + housekeeping -----------
// Cross-class IoU is exactly 0 (class offsets are multiples of 4096, raw boxes
// in [-0.5,1.5]) -> reference greedy loop decomposes by class.
__global__ void __launch_bounds__(CPB * 32) k_nms(float* __restrict__ out)
{
    const int BLOCKS_PER_B = NCLS / CPB;              // 10
    int b    = blockIdx.x / BLOCKS_PER_B;
    int s    = blockIdx.x % BLOCKS_PER_B;
    int tid  = threadIdx.x;
    int wrp  = tid >> 5;
    int lane = tid & 31;
    int c    = s * CPB + wrp;

    __shared__ unsigned short sList[CPB][MAXC];       // 16000 B

    // housekeeping 1: zero this block's slice of g_hist (replay invariant)
    {
        int lo = s * 410;
        int hi = lo + 410; if (hi > BINS) hi = BINS;
        for (int i = lo + tid; i < hi; i += CPB * 32)
            g_hist[b * BINS + i] = 0u;
    }
    // housekeeping 2: zero rows for empty ranks (ranks are contiguous 0..cnt-1)
    int cnt = __ldg(&g_cnt[b]);
    {
        int start = cnt < MAXC ? cnt : MAXC;
        for (int r = start + s * (CPB * 32) + tid; r < MAXC; r += BLOCKS_PER_B * CPB * 32) {
            int o = b * MAXC + r;
            float2* row = (float2*)(out + (size_t)o * 6);
            row[0] = make_float2(0.f, 0.f);
            row[1] = make_float2(0.f, 0.f);
            row[2] = make_float2(0.f, 0.f);
            out[(size_t)BATCH * MAXC * 6 + o] = 0.f;
        }
    }

    // ---- gather: mask -> rank list in SMEM (and reset mask for replay) ----
    int mi = (b * NCLS + c) * 32 + lane;
    unsigned word = __ldg(&g_mask[mi]);
    g_mask[mi] = 0u;

    int pc = __popc(word);
    int incl = pc;
#pragma unroll
    for (int off = 1; off < 32; off <<= 1) {
        int u = __shfl_up_sync(0xffffffffu, incl, off);
        if (lane >= off) incl += u;
    }
    int excl  = incl - pc;
    int total = __shfl_sync(0xffffffffu, incl, 31);

    {
        unsigned m = word; int o = excl;
        while (m) {
            int p = __ffs(m) - 1;
            m &= m - 1;
            sList[wrp][o++] = (unsigned short)(lane * 32 + p);
        }
    }
    __syncwarp();

    // ---- greedy NMS: prefetch chunk to registers, serial loop on shuffles ----
    int   nk = 0;
    float kx1 = 0, ky1 = 0, kx2 = 0, ky2 = 0, ka = 0;

    for (int base = 0; base < total; base += 32) {
        int j = base + lane;
        int ri = 0;
        float4 qb = make_float4(0.f, 0.f, 0.f, 0.f);
        float  qa_ = 0.f;
        if (j < total) {
            ri = (int)sList[wrp][j];
            int o = b * MAXC + ri;
            qb  = __ldg(&g_nbox[o]);
            qa_ = __ldg(&g_na[o]);
        }
        int nl = total - base; if (nl > 32) nl = 32;
        int keptflag = 0;

        for (int k = 0; k < nl; ++k) {
            float qx1 = __shfl_sync(0xffffffffu, qb.x, k);
            float qy1 = __shfl_sync(0xffffffffu, qb.y, k);
            float qx2 = __shfl_sync(0xffffffffu, qb.z, k);
            float qy2 = __shfl_sync(0xffffffffu, qb.w, k);
            float qa  = __shfl_sync(0xffffffffu, qa_,  k);

            int sup = 0;
            if (lane < nk) {
                float ltx = fmaxf(kx1, qx1);
                float lty = fmaxf(ky1, qy1);
                float rbx = fminf(kx2, qx2);
                float rby = fminf(ky2, qy2);
                float ww  = fmaxf(__fsub_rn(rbx, ltx), 0.0f);
                float hh  = fmaxf(__fsub_rn(rby, lty), 0.0f);
                float inter = __fmul_rn(ww, hh);
                float den = __fadd_rn(__fsub_rn(__fadd_rn(ka, qa), inter), 1e-7f);
                sup = (__fdiv_rn(inter, den) > IOU_T) ? 1 : 0;
            }
            unsigned sb = __ballot_sync(0xffffffffu, sup);
            if (!sb) {
                if (lane == nk) { kx1 = qx1; ky1 = qy1; kx2 = qx2; ky2 = qy2; ka = qa; }
                nk++;
                if (lane == k) keptflag = 1;
            }
        }

        // owning lane writes its output row (outside the dependent chain)
        if (j < total) {
            int o = b * MAXC + ri;
            float* rs = out + (size_t)o * 6;
            if (keptflag) {
                float4 rb = __ldg(&g_rbox[o]);
                rs[0] = rb.x; rs[1] = rb.y; rs[2] = rb.z; rs[3] = rb.w;
                rs[4] = __ldg(&g_conf[o]);
                rs[5] = (float)c;
                out[(size_t)BATCH * MAXC * 6 + o] = 1.0f;
            } else {
                rs[0] = 0.f; rs[1] = 0.f; rs[2] = 0.f;
                rs[3] = 0.f; rs[4] = 0.f; rs[5] = 0.f;
                out[(size_t)BATCH * MAXC * 6 + o] = 0.f;
            }
        }
    }
}

// ---------------- launch ----------------
extern "C" void kernel_launch(void* const* d_in, const int* in_sizes, int n_in,
                              void* d_out, int out_size)
{
    (void)in_sizes; (void)n_in; (void)out_size;
    const float* pred = (const float*)d_in[0];
    float* out = (float*)d_out;

    k_score<<<SGRID, 512>>>(pred);                     // persistent, 1 wave
    k_prep<<<BATCH * PSLICE, 1024>>>();                // 128 blocks
    k_nms<<<BATCH * (NCLS / CPB), CPB * 32>>>(out);    // 160 blocks
}